// round 4
// baseline (speedup 1.0000x reference)
#include <cuda_runtime.h>
#include <math_constants.h>

#define K 48
#define STOPID 47

// ---------- packed f32x2 helpers (Blackwell sm_103a) ----------
__device__ __forceinline__ unsigned long long pack2(float x, float y) {
    unsigned long long r;
    asm("mov.b64 %0, {%1, %2};" : "=l"(r)
        : "r"(__float_as_uint(x)), "r"(__float_as_uint(y)));
    return r;
}
__device__ __forceinline__ void unpack2(unsigned long long v, float& x, float& y) {
    unsigned int a, b;
    asm("mov.b64 {%0, %1}, %2;" : "=r"(a), "=r"(b) : "l"(v));
    x = __uint_as_float(a);
    y = __uint_as_float(b);
}
__device__ __forceinline__ unsigned long long fma2(unsigned long long a,
                                                   unsigned long long b,
                                                   unsigned long long c) {
    unsigned long long d;
    asm("fma.rn.f32x2 %0, %1, %2, %3;" : "=l"(d) : "l"(a), "l"(b), "l"(c));
    return d;
}
__device__ __forceinline__ unsigned long long add2(unsigned long long a,
                                                   unsigned long long b) {
    unsigned long long d;
    asm("add.rn.f32x2 %0, %1, %2;" : "=l"(d) : "l"(a), "l"(b));
    return d;
}

// One warp per batch sequence. 4 warps (4 batches) per CTA so warps land on
// all 4 SMSPs. Lane l (l<24) owns state rows {2l, 2l+1}; E=exp(trans) is held
// as 48 packed-f32x2 registers per lane. p is exchanged via a per-warp,
// double-buffered, duplicated shared array (96 floats/buffer) so the matvec
// consumes it as 24 broadcast LDS.128, each feeding two f32x2 FMAs.
__global__ __launch_bounds__(128) void crf_fwd_kernel(
    const float* __restrict__ h_tag,   // [B, T, K]
    const float* __restrict__ mask,    // [B, T]
    const float* __restrict__ trans,   // [K, K]
    float* __restrict__ out,           // [B]
    int B, int T)
{
    __shared__ __align__(16) float sp[4][2][96];

    const int wid  = threadIdx.x >> 5;
    const int lane = threadIdx.x & 31;
    const int b    = blockIdx.x * 4 + wid;
    if (b >= B) return;

    const bool act = lane < 24;
    const int row0 = 2 * lane;

    // ---- precompute E packed per lane: E2[j] = (exp(trans[2l][j]), exp(trans[2l+1][j]))
    unsigned long long E2[K];
    if (act) {
        const float* t0 = trans + row0 * K;
#pragma unroll
        for (int j = 0; j < K; j++)
            E2[j] = pack2(__expf(t0[j]), __expf(t0[K + j]));
    } else {
#pragma unroll
        for (int j = 0; j < K; j++) E2[j] = 0ULL;
    }

    const float* hb = h_tag + (size_t)b * T * K;
    const float* mb = mask + (size_t)b * T;

    // normalized scores: r = score - c, c0 = -1e4 (NEG), so r=0 except STOP=+1e4
    float rx, ry, c = -1.0e4f;
    if (act) {
        rx = 0.0f;                                   // row0 even, never STOP
        ry = (row0 + 1 == STOPID) ? 1.0e4f : 0.0f;
    } else {
        rx = -1.0e30f;
        ry = -1.0e30f;
    }

    // software pipeline (depth 2) for emit / mask
    float2 em0 = make_float2(0.f, 0.f), em1 = make_float2(0.f, 0.f);
    float mk0 = 0.f, mk1 = 0.f;
    if (act) em0 = *(const float2*)(hb + row0);
    mk0 = mb[0];
    if (T > 1) {
        if (act) em1 = *(const float2*)(hb + K + row0);
        mk1 = mb[1];
    }

    float* bufA = sp[wid][0];
    float* bufB = sp[wid][1];

    for (int t = 0; t < T; t++) {
        // p = exp(r), clamped high side so (huge p) * (E==0) stays 0*finite, never inf*0
        float p0 = __expf(fminf(rx, 70.0f));
        float p1 = __expf(fminf(ry, 70.0f));
        float* buf = (t & 1) ? bufB : bufA;
        if (act) {
            *(float2*)(buf + 4 * lane)     = make_float2(p0, p0);
            *(float2*)(buf + 4 * lane + 2) = make_float2(p1, p1);
        }
        __syncwarp();

        // prefetch t+2 (hides DRAM latency behind the matvec)
        float2 emn = make_float2(0.f, 0.f);
        float mkn = 0.f;
        if (t + 2 < T) {
            if (act) emn = *(const float2*)(hb + (size_t)(t + 2) * K + row0);
            mkn = mb[t + 2];
        }

        // matvec: (sum_{2l}, sum_{2l+1}) = sum_j E2[j] * (p_j, p_j)
        unsigned long long a0 = 0ULL, a1 = 0ULL, a2 = 0ULL, a3 = 0ULL;
        const ulonglong2* pv = (const ulonglong2*)buf;
#pragma unroll
        for (int q = 0; q < 24; q += 2) {
            ulonglong2 v0 = pv[q];
            ulonglong2 v1 = pv[q + 1];
            a0 = fma2(E2[2 * q],     v0.x, a0);
            a1 = fma2(E2[2 * q + 1], v0.y, a1);
            a2 = fma2(E2[2 * q + 2], v1.x, a2);
            a3 = fma2(E2[2 * q + 3], v1.y, a3);
        }
        unsigned long long s = add2(add2(a0, a1), add2(a2, a3));
        float sx, sy;
        unpack2(s, sx, sy);

        float n0 = em0.x + __logf(sx);   // __logf(0) = -inf is intended (barrier rows)
        float n1 = em0.y + __logf(sy);

        bool upd = (mk0 != 0.0f);        // mask is exactly 0/1 -> select == arithmetic blend
        rx = upd ? n0 : rx;
        ry = upd ? n1 : ry;

        // periodic renormalization: keep r bounded (drift ~ +4.4/step)
        if ((t & 3) == 3) {
            float d = __shfl_sync(0xffffffffu, rx, 0);  // row 0 is always finite
            rx -= d;
            ry -= d;
            c += d;
        }

        em0 = em1; em1 = emn;
        mk0 = mk1; mk1 = mkn;
    }

    // finalize: out[b] = c + lse_k( r_k + trans[STOP][k] )
    float v0 = -CUDART_INF_F, v1 = -CUDART_INF_F;
    if (act) {
        v0 = rx + trans[STOPID * K + row0];
        v1 = ry + trans[STOPID * K + row0 + 1];
    }
    float m = fmaxf(v0, v1);
#pragma unroll
    for (int o = 16; o; o >>= 1)
        m = fmaxf(m, __shfl_xor_sync(0xffffffffu, m, o));
    float ssum = __expf(v0 - m) + __expf(v1 - m);
#pragma unroll
    for (int o = 16; o; o >>= 1)
        ssum += __shfl_xor_sync(0xffffffffu, ssum, o);
    if (lane == 0) out[b] = c + m + __logf(ssum);
}

extern "C" void kernel_launch(void* const* d_in, const int* in_sizes, int n_in,
                              void* d_out, int out_size)
{
    // Identify inputs by size (robust to ordering):
    //   h_tag = largest (B*T*K), trans = smallest (K*K), mask = the other (B*T)
    int iH = 0, iT = 0;
    for (int i = 1; i < 3; i++) {
        if (in_sizes[i] > in_sizes[iH]) iH = i;
        if (in_sizes[i] < in_sizes[iT]) iT = i;
    }
    int iM = 3 - iH - iT;

    const float* h_tag = (const float*)d_in[iH];
    const float* mask  = (const float*)d_in[iM];
    const float* trans = (const float*)d_in[iT];
    float* out = (float*)d_out;

    int B = out_size;             // 512
    int T = in_sizes[iM] / B;     // 1024

    dim3 block(128);
    dim3 grid((B + 3) / 4);
    crf_fwd_kernel<<<grid, block>>>(h_tag, mask, trans, out, B, T);
}

// round 5
// speedup vs baseline: 3.7683x; 3.7683x over previous
#include <cuda_runtime.h>

#define K 48
#define STOPID 47
#define CHUNK 16
#define NWARP 4
#define CLAMPV 1e32f

typedef unsigned long long ull;

// ---------- packed f32x2 helpers (Blackwell sm_103a) ----------
__device__ __forceinline__ ull pack2(float x, float y) {
    ull r;
    asm("mov.b64 %0, {%1, %2};" : "=l"(r)
        : "r"(__float_as_uint(x)), "r"(__float_as_uint(y)));
    return r;
}
__device__ __forceinline__ void unpack2(ull v, float& x, float& y) {
    unsigned int a, b;
    asm("mov.b64 {%0, %1}, %2;" : "=r"(a), "=r"(b) : "l"(v));
    x = __uint_as_float(a);
    y = __uint_as_float(b);
}
__device__ __forceinline__ ull fma2(ull a, ull b, ull c) {
    ull d;
    asm("fma.rn.f32x2 %0, %1, %2, %3;" : "=l"(d) : "l"(a), "l"(b), "l"(c));
    return d;
}
__device__ __forceinline__ ull add2(ull a, ull b) {
    ull d;
    asm("add.rn.f32x2 %0, %1, %2;" : "=l"(d) : "l"(a), "l"(b));
    return d;
}
__device__ __forceinline__ void cp_async16(unsigned int s, const void* g) {
    asm volatile("cp.async.cg.shared.global [%0], [%1], 16;" :: "r"(s), "l"(g));
}

// One warp per sequence. State kept in probability space p = exp(score - c):
//   p' = exp(emit) * (E p),  E = exp(trans)  (precomputed in 96 packed regs/lane)
// exp(emit) comes from cp.async-prefetched shared chunks (16 steps ahead) and
// is computed OFF the serial dependency chain. No exp/log on the chain at all.
// Renorm every 8 steps: divide by lane0's p (shfl + MUFU.RCP), c += log(d).
__global__ __launch_bounds__(128, 1) void crf_fwd_kernel(
    const float* __restrict__ h_tag,   // [B, T, K]
    const float* __restrict__ mask,    // [B, T]
    const float* __restrict__ trans,   // [K, K]
    float* __restrict__ out,           // [B]
    int B, int T)
{
    __shared__ __align__(16) float emb[NWARP][2][CHUNK * K];  // emit chunks
    __shared__ __align__(16) float mkb[NWARP][2][CHUNK];      // mask chunks
    __shared__ __align__(16) float pb [NWARP][2][K];          // p exchange (dbl buf)

    const int wid  = threadIdx.x >> 5;
    const int lane = threadIdx.x & 31;
    const int b    = blockIdx.x * NWARP + wid;
    if (b >= B) return;

    const bool act  = lane < 24;
    const int  row0 = 2 * lane;

    // E packed across j: E2a[q] = (E[i0][2q], E[i0][2q+1]), i0 = 2*lane
    ull E2a[24], E2b[24];
    if (act) {
        const float* t0 = trans + row0 * K;
        const float* t1 = t0 + K;
#pragma unroll
        for (int q = 0; q < 24; q++) {
            E2a[q] = pack2(__expf(t0[2 * q]), __expf(t0[2 * q + 1]));
            E2b[q] = pack2(__expf(t1[2 * q]), __expf(t1[2 * q + 1]));
        }
    } else {
#pragma unroll
        for (int q = 0; q < 24; q++) { E2a[q] = 0ULL; E2b[q] = 0ULL; }
    }

    const float* hb = h_tag + (size_t)b * T * K;
    const float* mb = mask + (size_t)b * T;

    // initial: score = NEG except STOP=0; represent as c=-1e4, p=1 for normal
    // states (exact), p_STOP clamped to 1e32 (truncation feeds only the PAD
    // track, which sits e^4500 below the answer — validated in R3).
    float p0, p1, c = -1.0e4f;
    if (act) { p0 = 1.0f; p1 = (row0 + 1 == STOPID) ? CLAMPV : 1.0f; }
    else     { p0 = 0.0f; p1 = 0.0f; }
    if (act) *(float2*)(&pb[wid][0][row0]) = make_float2(p0, p1);

    const int nc = (T + CHUNK - 1) / CHUNK;

    // prefetch chunk 0
    {
        unsigned int se = (unsigned int)__cvta_generic_to_shared(&emb[wid][0][0]);
#pragma unroll
        for (int i = 0; i < 6; i++) {
            int seg = lane + 32 * i;
            if ((size_t)(seg + 1) * 4 <= (size_t)T * K)
                cp_async16(se + seg * 16, hb + seg * 4);
        }
        unsigned int sm = (unsigned int)__cvta_generic_to_shared(&mkb[wid][0][0]);
        if (lane < 4 && (lane + 1) * 4 <= T)
            cp_async16(sm + lane * 16, mb + lane * 4);
        asm volatile("cp.async.commit_group;");
    }

    int t = 0;
    for (int ch = 0; ch < nc; ch++) {
        const int cb = ch & 1;
        // prefetch chunk ch+1 into the other buffer, then wait for chunk ch
        if (ch + 1 < nc) {
            const int t0n = (ch + 1) * CHUNK;
            const float* srcE = hb + (size_t)t0n * K;
            unsigned int se = (unsigned int)__cvta_generic_to_shared(&emb[wid][(ch + 1) & 1][0]);
#pragma unroll
            for (int i = 0; i < 6; i++) {
                int seg = lane + 32 * i;
                if ((size_t)t0n * K + (size_t)(seg + 1) * 4 <= (size_t)T * K)
                    cp_async16(se + seg * 16, srcE + seg * 4);
            }
            unsigned int sm = (unsigned int)__cvta_generic_to_shared(&mkb[wid][(ch + 1) & 1][0]);
            if (lane < 4 && t0n + (lane + 1) * 4 <= T)
                cp_async16(sm + lane * 16, mb + t0n + lane * 4);
            asm volatile("cp.async.commit_group;");
            asm volatile("cp.async.wait_group 1;");
        } else {
            asm volatile("cp.async.wait_group 0;");
        }

        const int steps = min(CHUNK, T - ch * CHUNK);
        for (int s = 0; s < steps; s++, t++) {
            __syncwarp();   // chunk data + previous step's p visible

            // off-chain: emit -> exp(emit), mask
            float2 em = *(const float2*)(&emb[wid][cb][s * K + (act ? row0 : 0)]);
            float eex = __expf(em.x);
            float eey = __expf(em.y);
            float mk  = mkb[wid][cb][s];

            // matvec: s_i = sum_j E[i][j] p[j], 12 LDS.128 + 48 fma2
            const ulonglong2* pu = (const ulonglong2*)(&pb[wid][t & 1][0]);
            ull aA[4] = {0ULL, 0ULL, 0ULL, 0ULL};
            ull aB[4] = {0ULL, 0ULL, 0ULL, 0ULL};
#pragma unroll
            for (int m = 0; m < 12; m++) {
                ulonglong2 u = pu[m];
                aA[(2 * m) & 3]     = fma2(E2a[2 * m],     u.x, aA[(2 * m) & 3]);
                aB[(2 * m) & 3]     = fma2(E2b[2 * m],     u.x, aB[(2 * m) & 3]);
                aA[(2 * m + 1) & 3] = fma2(E2a[2 * m + 1], u.y, aA[(2 * m + 1) & 3]);
                aB[(2 * m + 1) & 3] = fma2(E2b[2 * m + 1], u.y, aB[(2 * m + 1) & 3]);
            }
            ull sA = add2(add2(aA[0], aA[2]), add2(aA[1], aA[3]));
            ull sB = add2(add2(aB[0], aB[2]), add2(aB[1], aB[3]));
            float a0, a1, b0, b1;
            unpack2(sA, a0, a1);
            unpack2(sB, b0, b1);

            float pn0 = fminf(eex * (a0 + a1), CLAMPV);
            float pn1 = fminf(eey * (b0 + b1), CLAMPV);

            bool upd = (mk != 0.0f);
            p0 = upd ? pn0 : p0;
            p1 = upd ? pn1 : p1;

            // renorm every 8 steps (growth ~4.4/step; headroom to e^88 is ample)
            if ((t & 7) == 7) {
                float d = __shfl_sync(0xffffffffu, p0, 0);  // state 0: always finite >0
                float sc;
                asm("rcp.approx.f32 %0, %1;" : "=f"(sc) : "f"(d));
                p0 *= sc;
                p1 *= sc;
                c += __logf(d);
            }

            if (act) *(float2*)(&pb[wid][(t + 1) & 1][row0]) = make_float2(p0, p1);
        }
    }

    // finalize: out = c + log( sum_k p_k * exp(trans[STOP][k]) )
    float v = 0.0f;
    if (act) {
        v = p0 * __expf(trans[STOPID * K + row0])
          + p1 * __expf(trans[STOPID * K + row0 + 1]);
    }
#pragma unroll
    for (int o = 16; o; o >>= 1)
        v += __shfl_xor_sync(0xffffffffu, v, o);
    if (lane == 0) out[b] = c + __logf(v);
}

extern "C" void kernel_launch(void* const* d_in, const int* in_sizes, int n_in,
                              void* d_out, int out_size)
{
    // Identify inputs by size: h_tag = largest, trans = smallest, mask = other
    int iH = 0, iT = 0;
    for (int i = 1; i < 3; i++) {
        if (in_sizes[i] > in_sizes[iH]) iH = i;
        if (in_sizes[i] < in_sizes[iT]) iT = i;
    }
    int iM = 3 - iH - iT;

    const float* h_tag = (const float*)d_in[iH];
    const float* mask  = (const float*)d_in[iM];
    const float* trans = (const float*)d_in[iT];
    float* out = (float*)d_out;

    int B = out_size;             // 512
    int T = in_sizes[iM] / B;     // 1024

    dim3 block(128);
    dim3 grid((B + NWARP - 1) / NWARP);
    crf_fwd_kernel<<<grid, block>>>(h_tag, mask, trans, out, B, T);
}